// round 1
// baseline (speedup 1.0000x reference)
#include <cuda_runtime.h>

// Problem constants (from reference): B=8, T=2048, V=1024.
// Math: with c = idx[b,t], eq(s)=[idx(b,s)==c], Pc(s)=inclusive prefix count,
//   A(s) = (w0-w2)*eq(s) + (w1-w2)*eq(s-1) + w2*Pc(s)
//   logits[b,t,v] = sum_{s<=t, idx(b,s)==v} A(s)
//   out = softmax(logits, axis=-1)
// One block per output row (b,t): scatter A into shared acc[V], fused softmax.

namespace {
constexpr int T  = 2048;
constexpr int V  = 1024;
constexpr int B  = 8;
constexpr int NT = 256;        // threads per block
constexpr int NW = NT / 32;    // warps per block
constexpr int CH = 1024;       // s-chunk per iteration (4 per thread)
}

__global__ __launch_bounds__(NT) void min_model_kernel(
    const int* __restrict__ gidx,     // [B, T] int32
    const float* __restrict__ vw,     // [4] float (w3 unused: masked by tril)
    float* __restrict__ out)          // [B, T, V] float
{
    __shared__ float acc[V];
    __shared__ int   sidx[T];
    __shared__ int   wsum[NW];
    __shared__ float rbuf[NW];

    const int t    = blockIdx.x;
    const int b    = blockIdx.y;
    const int tid  = threadIdx.x;
    const int lane = tid & 31;
    const int warp = tid >> 5;

    // Cache the idx row in shared (8 KB), vectorized; L1/L2 serve the 2048
    // blocks that share each row.
    {
        const int4* src = reinterpret_cast<const int4*>(gidx + b * T);
        int4* dst = reinterpret_cast<int4*>(sidx);
        #pragma unroll
        for (int i = 0; i < T / 4; i += NT)
            dst[i + tid] = src[i + tid];
    }
    #pragma unroll
    for (int i = 0; i < V; i += NT)
        acc[i + tid] = 0.f;
    __syncthreads();

    const int   c  = sidx[t];
    const float w0 = vw[0], w1 = vw[1], w2 = vw[2];
    const float a0 = w0 - w2, a1 = w1 - w2;

    int carry = 0;  // Pc up to end of previous chunk
    for (int base = 0; base <= t; base += CH) {
        const int s0 = base + tid * 4;
        // base is a multiple of 1024 and <= t <= 2047, so s0+3 <= 2047: safe.
        const int4 tk = reinterpret_cast<const int4*>(sidx)[(base >> 2) + tid];
        const int prev = (s0 > 0) ? sidx[s0 - 1] : -1;

        const int e0 = (tk.x == c), e1 = (tk.y == c),
                  e2 = (tk.z == c), e3 = (tk.w == c);
        const int em0 = (prev == c);
        const int p0 = e0, p1 = p0 + e1, p2 = p1 + e2, p3 = p2 + e3;

        // Warp-inclusive scan of per-thread counts (thread order == s order).
        int incl = p3;
        #pragma unroll
        for (int o = 1; o < 32; o <<= 1) {
            int n = __shfl_up_sync(0xffffffffu, incl, o);
            if (lane >= o) incl += n;
        }
        if (lane == 31) wsum[warp] = incl;
        const int texcl = incl - p3;
        __syncthreads();

        int wexcl = 0, tot = 0;
        if (lane == 0) {
            #pragma unroll
            for (int w = 0; w < NW; w++) {
                int x = wsum[w];
                tot += x;
                if (w < warp) wexcl += x;
            }
        }
        wexcl = __shfl_sync(0xffffffffu, wexcl, 0);
        tot   = __shfl_sync(0xffffffffu, tot, 0);

        // If c never occurred up to the end of this chunk, every A is 0.
        if (carry + tot) {
            const int pb = carry + wexcl + texcl;
            int pc, em;
            pc = pb + p0; em = em0;
            if (s0 + 0 <= t && (pc | em))
                atomicAdd(&acc[tk.x], fmaf((float)pc, w2, a0 * (float)e0 + a1 * (float)em));
            pc = pb + p1; em = e0;
            if (s0 + 1 <= t && (pc | em))
                atomicAdd(&acc[tk.y], fmaf((float)pc, w2, a0 * (float)e1 + a1 * (float)em));
            pc = pb + p2; em = e1;
            if (s0 + 2 <= t && (pc | em))
                atomicAdd(&acc[tk.z], fmaf((float)pc, w2, a0 * (float)e2 + a1 * (float)em));
            pc = pb + p3; em = e2;
            if (s0 + 3 <= t && (pc | em))
                atomicAdd(&acc[tk.w], fmaf((float)pc, w2, a0 * (float)e3 + a1 * (float)em));
        }
        carry += tot;
        __syncthreads();  // wsum reuse + acc visibility
    }

    // ---- fused softmax over acc[0..V) ----
    const int i0 = tid * 4;
    const float4 a4 = *reinterpret_cast<const float4*>(&acc[i0]);

    float vmax = fmaxf(fmaxf(a4.x, a4.y), fmaxf(a4.z, a4.w));
    #pragma unroll
    for (int o = 16; o; o >>= 1)
        vmax = fmaxf(vmax, __shfl_xor_sync(0xffffffffu, vmax, o));
    if (lane == 0) rbuf[warp] = vmax;
    __syncthreads();
    float bmax = rbuf[0];
    #pragma unroll
    for (int w = 1; w < NW; w++) bmax = fmaxf(bmax, rbuf[w]);
    __syncthreads();  // protect rbuf before reuse for the sum

    const float x0 = __expf(a4.x - bmax);
    const float x1 = __expf(a4.y - bmax);
    const float x2 = __expf(a4.z - bmax);
    const float x3 = __expf(a4.w - bmax);
    float ssum = (x0 + x1) + (x2 + x3);
    #pragma unroll
    for (int o = 16; o; o >>= 1)
        ssum += __shfl_xor_sync(0xffffffffu, ssum, o);
    if (lane == 0) rbuf[warp] = ssum;
    __syncthreads();
    float bs = 0.f;
    #pragma unroll
    for (int w = 0; w < NW; w++) bs += rbuf[w];

    const float inv = 1.0f / bs;
    const float4 o4 = make_float4(x0 * inv, x1 * inv, x2 * inv, x3 * inv);
    *reinterpret_cast<float4*>(out + (size_t)(b * T + t) * V + i0) = o4;
}

extern "C" void kernel_launch(void* const* d_in, const int* in_sizes, int n_in,
                              void* d_out, int out_size) {
    const int*   idx = (const int*)d_in[0];
    const float* vw  = (const float*)d_in[1];
    float*       out = (float*)d_out;
    (void)in_sizes; (void)n_in; (void)out_size;

    dim3 grid(T, B);
    min_model_kernel<<<grid, NT>>>(idx, vw, out);
}

// round 2
// speedup vs baseline: 1.2107x; 1.2107x over previous
#include <cuda_runtime.h>

// B=8, T=2048, V=1024.
// With c = idx[b,t], q_1..q_m = occurrences of c in [0..t], Cv(r) = prefix hist:
//   L_t[v] = w2*( m*Cv(t) - sum_j Cv(q_j-1) ) + a0*m*[v==c]
//            + a1*#{j : q_j+1 <= t and idx(q_j+1)==v}
//   out = softmax(L_t)
// Prefix hists are checkpointed every SEG=32 positions (u16, global, L2-resident);
// sub-checkpoint remainders are tiny shared-atomic scatters (~16 elems each).

namespace {
constexpr int B = 8, T = 2048, V = 1024;
constexpr int SEG = 32, NSEG = T / SEG;   // 64 checkpoints per row
constexpr int NT = 256;
constexpr int NW = NT / 32;
}

// g_cp[b][p][v] = #{s < 32*p : idx(b,s)==v}  (exclusive prefix histogram)
__device__ unsigned short g_cp[B][NSEG][V];
__device__ unsigned short g_row[B][T];

// ---- K1: per-segment histograms (also builds u16 row copy) ----
__global__ __launch_bounds__(NT) void k_seghist(const int* __restrict__ idx) {
    __shared__ int hist[V];
    const int p = blockIdx.x, b = blockIdx.y, tid = threadIdx.x;
    #pragma unroll
    for (int i = tid; i < V; i += NT) hist[i] = 0;
    __syncthreads();
    if (tid < SEG) {
        const int tok = idx[b * T + p * SEG + tid];
        g_row[b][p * SEG + tid] = (unsigned short)tok;
        atomicAdd(&hist[tok], 1);
    }
    __syncthreads();
    const int v0 = tid * 4;
    ushort4 o;
    o.x = (unsigned short)hist[v0 + 0];
    o.y = (unsigned short)hist[v0 + 1];
    o.z = (unsigned short)hist[v0 + 2];
    o.w = (unsigned short)hist[v0 + 3];
    *reinterpret_cast<ushort4*>(&g_cp[b][p][v0]) = o;
}

// ---- K2: in-place exclusive prefix over the 64 segments, per (b, v) ----
__global__ __launch_bounds__(NT) void k_prefix() {
    const int b = blockIdx.x;
    const int v = blockIdx.y * NT + threadIdx.x;
    unsigned run = 0;
    #pragma unroll
    for (int pc = 0; pc < 4; pc++) {
        unsigned x[16];
        #pragma unroll
        for (int k = 0; k < 16; k++) x[k] = g_cp[b][pc * 16 + k][v];
        #pragma unroll
        for (int k = 0; k < 16; k++) {
            const unsigned y = run;
            run += x[k];
            g_cp[b][pc * 16 + k][v] = (unsigned short)y;
        }
    }
}

// ---- K3: one block per output row (b,t) ----
__global__ __launch_bounds__(NT) void k_main(const float* __restrict__ vw,
                                             float* __restrict__ out) {
    __shared__ unsigned short srow[T];    // 4 KB
    __shared__ float acc[V];              // 4 KB (remainder corrections)
    __shared__ unsigned short qlist[T];   // 4 KB (occurrence positions)
    __shared__ int qcnt;
    __shared__ float rbuf[NW];

    const int t = blockIdx.x, b = blockIdx.y;
    const int tid = threadIdx.x, lane = tid & 31, warp = tid >> 5;

    // Row load: thread tid holds tokens [tid*8 .. tid*8+7] in one uint4.
    const uint4 rowv = reinterpret_cast<const uint4*>(g_row[b])[tid];
    reinterpret_cast<uint4*>(srow)[tid] = rowv;
    reinterpret_cast<float4*>(acc)[tid] = make_float4(0.f, 0.f, 0.f, 0.f);
    if (tid == 0) qcnt = 0;
    __syncthreads();

    const int c = srow[t];
    const float w0 = vw[0], w1 = vw[1], w2 = vw[2];
    const float a0 = w0 - w2, a1 = w1 - w2;

    // Enumerate occurrences of c in [0..t] from the registers we already hold.
    {
        const int s0 = tid * 8;
        unsigned tk[8];
        tk[0] = rowv.x & 0xFFFFu; tk[1] = rowv.x >> 16;
        tk[2] = rowv.y & 0xFFFFu; tk[3] = rowv.y >> 16;
        tk[4] = rowv.z & 0xFFFFu; tk[5] = rowv.z >> 16;
        tk[6] = rowv.w & 0xFFFFu; tk[7] = rowv.w >> 16;
        unsigned mask = 0;
        #pragma unroll
        for (int k = 0; k < 8; k++)
            if (s0 + k <= t && tk[k] == (unsigned)c) mask |= 1u << k;
        if (mask) {
            int base = atomicAdd(&qcnt, __popc(mask));
            while (mask) {
                const int k = __ffs(mask) - 1;
                mask &= mask - 1;
                qlist[base++] = (unsigned short)(s0 + k);
            }
        }
    }
    __syncthreads();
    const int m = qcnt;            // >= 1 (t itself qualifies)
    const float fm = (float)m;

    // Register part: w2 * ( m*CP[p_t][v] - sum_j CP[p_j][v] ), 4 v's per thread.
    const int v0 = tid * 4;
    float4 r;
    {
        const ushort4 cpt = *reinterpret_cast<const ushort4*>(&g_cp[b][t >> 5][v0]);
        r.x = fm * (float)cpt.x; r.y = fm * (float)cpt.y;
        r.z = fm * (float)cpt.z; r.w = fm * (float)cpt.w;
    }
    for (int j = 0; j < m; j++) {
        const int q = qlist[j];
        if (q == 0) continue;                       // Cv(-1) = 0
        const ushort4 cq =
            *reinterpret_cast<const ushort4*>(&g_cp[b][(q - 1) >> 5][v0]);
        r.x -= (float)cq.x; r.y -= (float)cq.y;
        r.z -= (float)cq.z; r.w -= (float)cq.w;
    }

    // Shared-atomic corrections (tiny: <= 32 per group, ~m+1 groups).
    if (warp == 0) {
        const int s = (t & ~(SEG - 1)) + lane;      // remainder of Cv(t)
        if (s <= t) atomicAdd(&acc[srow[s]], w2 * fm);
        if (lane == 0) atomicAdd(&acc[c], a0 * fm); // a0 * m at v == c
    }
    for (int j = warp; j < m; j += NW) {
        const int q = qlist[j];
        if (q > 0) {
            const int s = ((q - 1) & ~(SEG - 1)) + lane;  // remainder of Cv(q-1)
            if (s <= q - 1) atomicAdd(&acc[srow[s]], -w2);
        }
        if (lane == 0 && q + 1 <= t)                       // bigram c -> next
            atomicAdd(&acc[srow[q + 1]], a1);
    }
    __syncthreads();

    // Assemble logits and fused softmax.
    const float4 av = *reinterpret_cast<const float4*>(&acc[v0]);
    float4 a4;
    a4.x = fmaf(w2, r.x, av.x);
    a4.y = fmaf(w2, r.y, av.y);
    a4.z = fmaf(w2, r.z, av.z);
    a4.w = fmaf(w2, r.w, av.w);

    float vmax = fmaxf(fmaxf(a4.x, a4.y), fmaxf(a4.z, a4.w));
    #pragma unroll
    for (int o = 16; o; o >>= 1)
        vmax = fmaxf(vmax, __shfl_xor_sync(0xffffffffu, vmax, o));
    if (lane == 0) rbuf[warp] = vmax;
    __syncthreads();
    float bmax = rbuf[0];
    #pragma unroll
    for (int w = 1; w < NW; w++) bmax = fmaxf(bmax, rbuf[w]);
    __syncthreads();  // protect rbuf before reuse

    const float x0 = __expf(a4.x - bmax);
    const float x1 = __expf(a4.y - bmax);
    const float x2 = __expf(a4.z - bmax);
    const float x3 = __expf(a4.w - bmax);
    float ssum = (x0 + x1) + (x2 + x3);
    #pragma unroll
    for (int o = 16; o; o >>= 1)
        ssum += __shfl_xor_sync(0xffffffffu, ssum, o);
    if (lane == 0) rbuf[warp] = ssum;
    __syncthreads();
    float bs = 0.f;
    #pragma unroll
    for (int w = 0; w < NW; w++) bs += rbuf[w];

    const float inv = 1.0f / bs;
    const float4 o4 = make_float4(x0 * inv, x1 * inv, x2 * inv, x3 * inv);
    *reinterpret_cast<float4*>(out + (size_t)(b * T + t) * V + v0) = o4;
}

extern "C" void kernel_launch(void* const* d_in, const int* in_sizes, int n_in,
                              void* d_out, int out_size) {
    const int*   idx = (const int*)d_in[0];
    const float* vw  = (const float*)d_in[1];
    float*       out = (float*)d_out;
    (void)in_sizes; (void)n_in; (void)out_size;

    k_seghist<<<dim3(NSEG, B), NT>>>(idx);
    k_prefix<<<dim3(B, V / NT), NT>>>();
    k_main<<<dim3(T, B), NT>>>(vw, out);
}